// round 9
// baseline (speedup 1.0000x reference)
#include <cuda_runtime.h>
#include <cuda_fp16.h>
#include <math.h>
#include <stdint.h>

#define T 16384          // B*S tokens
#define D 1024
#define E 8
#define ROWCAP (2*T + E*128)
#define KCH 32           // k per pipeline stage
#define NC (D/KCH)       // 32 chunks
#define NSTAGE 4
// per-stage layout (bytes): Ahi[2][4096] Bhi[2][4096]
#define STAGE_B 16384
#define SMEM_DYN (1024 + NSTAGE*STAGE_B)

// ---------------- scratch ----------------------------------------------------
__device__ int   g_counts[E];
__device__ int   g_cursor[E];
__device__ int   g_off[E];
__device__ int   g_topk_e[2*T];
__device__ float g_topk_w[2*T];
__device__ int   g_perm[ROWCAP];
__device__ float g_permw[ROWCAP];
// preconverted fp16 operands
__device__ __half g_Xh[(size_t)T*D];
__device__ __half g_Weh[(size_t)E*D*D];
__device__ __half g_Woh[(size_t)D*D];
__device__ __half g_Ch[(size_t)T*D];   // combined expert output (atomic fp16 accum)

// ---------------- helpers ----------------------------------------------------
__device__ __forceinline__ uint32_t smem_u32(const void* p) {
    uint32_t a;
    asm("{ .reg .u64 t; cvta.to.shared.u64 t, %1; cvt.u32.u64 %0, t; }" : "=r"(a) : "l"(p));
    return a;
}

__device__ __forceinline__ void ldsm4(uint32_t* r, uint32_t a) {
    asm volatile("ldmatrix.sync.aligned.m8n8.x4.shared.b16 {%0,%1,%2,%3}, [%4];"
        : "=r"(r[0]), "=r"(r[1]), "=r"(r[2]), "=r"(r[3]) : "r"(a));
}

__device__ __forceinline__ void mma_f16(float* d, const uint32_t* a, const uint32_t* b) {
    asm volatile("mma.sync.aligned.m16n8k16.row.col.f32.f16.f16.f32 "
        "{%0,%1,%2,%3},{%4,%5,%6,%7},{%8,%9},{%0,%1,%2,%3};"
        : "+f"(d[0]), "+f"(d[1]), "+f"(d[2]), "+f"(d[3])
        : "r"(a[0]), "r"(a[1]), "r"(a[2]), "r"(a[3]), "r"(b[0]), "r"(b[1]));
}

__device__ __forceinline__ void cp16(uint32_t dst, const void* src) {
    asm volatile("cp.async.cg.shared.global [%0], [%1], 16;" :: "r"(dst), "l"(src));
}
#define CP_COMMIT() asm volatile("cp.async.commit_group;" ::: "memory")
#define CP_WAIT2()  asm volatile("cp.async.wait_group 2;" ::: "memory")

// swizzled byte offset within a 4KB (128 rows x 32B) k16 sub-tile
__device__ __forceinline__ int swz(int r, int h) {
    return (((r << 1) | h) ^ ((r >> 2) & 1)) << 4;
}

__device__ __forceinline__ uint2 pack4h(float4 v) {
    unsigned short h0 = __half_as_ushort(__float2half_rn(v.x));
    unsigned short h1 = __half_as_ushort(__float2half_rn(v.y));
    unsigned short h2 = __half_as_ushort(__float2half_rn(v.z));
    unsigned short h3 = __half_as_ushort(__float2half_rn(v.w));
    return make_uint2((uint32_t)h0 | ((uint32_t)h1 << 16),
                      (uint32_t)h2 | ((uint32_t)h3 << 16));
}

// ---------------- convert: fp32 -> fp16 --------------------------------------
__global__ __launch_bounds__(256) void k_convert_h(
    const float4* __restrict__ in, uint2* __restrict__ hi, int n4)
{
    for (int i = blockIdx.x * 256 + threadIdx.x; i < n4; i += gridDim.x * 256)
        hi[i] = pack4h(in[i]);
}

// ---------------- init / router(+X convert) / scan / scatter -----------------
__global__ void k_init() {
    int i = threadIdx.x;
    if (i < E) { g_counts[i] = 0; g_cursor[i] = 0; }
}

__global__ __launch_bounds__(256) void k_router(
    const float* __restrict__ X, const float* __restrict__ Wr,
    const float* __restrict__ br)
{
    __shared__ float4 sWr[E * D / 4];
    int tid = threadIdx.x;
    for (int i = tid; i < E * D / 4; i += 256) sWr[i] = ((const float4*)Wr)[i];
    __syncthreads();

    int warp = tid >> 5, lane = tid & 31;
    int t = blockIdx.x * 8 + warp;

    const float4* xi = (const float4*)(X + (size_t)t * D);
    uint2* xo = (uint2*)(g_Xh + (size_t)t * D);

    float acc[E];
#pragma unroll
    for (int e = 0; e < E; e++) acc[e] = 0.f;

    // single pass: convert to fp16 AND accumulate router logits
#pragma unroll
    for (int i = 0; i < D / 4 / 32; i++) {
        int idx = i * 32 + lane;
        float4 v = xi[idx];
        xo[idx] = pack4h(v);
#pragma unroll
        for (int e = 0; e < E; e++) {
            float4 w = sWr[e * (D / 4) + idx];
            acc[e] += v.x * w.x + v.y * w.y + v.z * w.z + v.w * w.w;
        }
    }
#pragma unroll
    for (int e = 0; e < E; e++) {
#pragma unroll
        for (int o = 16; o > 0; o >>= 1)
            acc[e] += __shfl_xor_sync(0xffffffffu, acc[e], o);
    }
    if (lane == 0) {
        float p[E], m = -1e30f;
#pragma unroll
        for (int e = 0; e < E; e++) { p[e] = acc[e] + br[e]; m = fmaxf(m, p[e]); }
        float s = 0.f;
#pragma unroll
        for (int e = 0; e < E; e++) { p[e] = expf(p[e] - m); s += p[e]; }
        float inv = 1.f / s;
#pragma unroll
        for (int e = 0; e < E; e++) p[e] *= inv;
        int e0 = 0;
#pragma unroll
        for (int e = 1; e < E; e++) if (p[e] > p[e0]) e0 = e;
        int e1 = (e0 == 0) ? 1 : 0;
#pragma unroll
        for (int e = 0; e < E; e++) if (e != e0 && p[e] > p[e1]) e1 = e;
        g_topk_e[2 * t + 0] = e0;  g_topk_w[2 * t + 0] = p[e0];
        g_topk_e[2 * t + 1] = e1;  g_topk_w[2 * t + 1] = p[e1];
        atomicAdd(&g_counts[e0], 1);
        atomicAdd(&g_counts[e1], 1);
    }
}

__global__ void k_scan() {
    if (threadIdx.x == 0) {
        int off = 0;
        for (int e = 0; e < E; e++) {
            g_off[e] = off;
            off += ((g_counts[e] + 127) / 128) * 128;
        }
    }
}

__global__ __launch_bounds__(256) void k_scatter() {
    int idx = blockIdx.x * 256 + threadIdx.x;
    if (idx >= 2 * T) return;
    int e = g_topk_e[idx];
    float w = g_topk_w[idx];
    int pos = atomicAdd(&g_cursor[e], 1);
    int slot = g_off[e] + pos;
    g_perm[slot]  = idx >> 1;
    g_permw[slot] = w;
}

// ===== shared compute: 2 k16 steps, single-pass fp16 =========================
#define COMPUTE_STAGE(bufbase)                                                \
    do {                                                                      \
        _Pragma("unroll")                                                     \
        for (int ks = 0; ks < 2; ks++) {                                      \
            uint32_t ahB = (bufbase) + ks * 4096;                             \
            uint32_t bhB = (bufbase) + 8192 + ks * 4096;                      \
            uint32_t ahi[4][4], bhi[2][4];                                    \
            _Pragma("unroll")                                                 \
            for (int mf = 0; mf < 4; mf++) ldsm4(ahi[mf], ahB + aoff[mf]);    \
            _Pragma("unroll")                                                 \
            for (int p = 0; p < 2; p++) ldsm4(bhi[p], bhB + boff[p]);         \
            _Pragma("unroll")                                                 \
            for (int mf = 0; mf < 4; mf++)                                    \
                _Pragma("unroll")                                             \
                for (int nf = 0; nf < 4; nf++)                                \
                    mma_f16(acc[mf][nf], ahi[mf], &bhi[nf >> 1][(nf & 1) * 2]); \
        }                                                                     \
    } while (0)

#define SETUP_LDSM_OFFS()                                                     \
    int aoff[4], boff[2];                                                     \
    {                                                                         \
        int ar = lane & 15, ah = lane >> 4;                                   \
        _Pragma("unroll")                                                     \
        for (int mf = 0; mf < 4; mf++) aoff[mf] = swz(wm * 64 + mf * 16 + ar, ah); \
        int bj = lane >> 3;                                                   \
        int bn = (lane & 7) + ((bj >> 1) << 3);                               \
        int bh_ = bj & 1;                                                     \
        _Pragma("unroll")                                                     \
        for (int p = 0; p < 2; p++) boff[p] = swz(wn * 32 + p * 16 + bn, bh_);\
    }

// 4 x 16B segments per thread per stage: part = seg>>9 (0=Ahi,1=Bhi)
#define ISSUE_STAGE(c)                                                        \
    do {                                                                      \
        uint32_t _sb = bufs_u + ((c) & (NSTAGE - 1)) * STAGE_B;               \
        int _k0 = (c) * KCH;                                                  \
        _Pragma("unroll")                                                     \
        for (int i = 0; i < 4; i++) cp16(_sb + dstoff[i], segp[i] + _k0);     \
    } while (0)

// ------- expert GEMM: Ch[tok] += fp16(w*(X[tok]@We[e]^T+be[e])) (atomic) -----
__global__ __launch_bounds__(256, 2) void k_expert_gemm(const float* __restrict__ be)
{
    int e = blockIdx.z;
    int cnt = g_counts[e];
    int row0 = blockIdx.y * 128;
    if (row0 >= cnt) return;
    int n0 = blockIdx.x * 128;
    int off = g_off[e];

    extern __shared__ char smem[];
    int* sTok = (int*)smem;
    float* sW = (float*)(smem + 512);
    uint32_t bufs_u = smem_u32(smem + 1024);

    int tid = threadIdx.x, lane = tid & 31, warp = tid >> 5;
    int wm = warp >> 2, wn = warp & 3;
    const __half* Whi = g_Weh + (size_t)e * D * D;

    if (tid < 128) {
        int rl = row0 + tid;
        bool v = rl < cnt;
        sTok[tid] = v ? g_perm[off + rl] : -1;
        sW[tid]   = v ? g_permw[off + rl] : 0.f;
    }
    __syncthreads();

    SETUP_LDSM_OFFS();

    const __half* segp[4];
    int dstoff[4];
#pragma unroll
    for (int i = 0; i < 4; i++) {
        int seg = i * 256 + tid;
        int part = seg >> 9;
        int r = (seg >> 2) & 127;
        int s = seg & 3;
        dstoff[i] = part * 8192 + (s >> 1) * 4096 + swz(r, s & 1);
        if (part == 0) {
            int tk = sTok[r]; if (tk < 0) tk = 0;   // garbage row masked in epilogue
            segp[i] = g_Xh + (size_t)tk * D + s * 8;
        } else {
            segp[i] = Whi + (size_t)(n0 + r) * D + s * 8;
        }
    }

    float acc[4][4][4];
#pragma unroll
    for (int mf = 0; mf < 4; mf++)
#pragma unroll
        for (int nf = 0; nf < 4; nf++)
#pragma unroll
            for (int q = 0; q < 4; q++) acc[mf][nf][q] = 0.f;

#pragma unroll
    for (int s = 0; s < NSTAGE - 1; s++) { ISSUE_STAGE(s); CP_COMMIT(); }

    for (int c = 0; c < NC; c++) {
        CP_WAIT2();
        __syncthreads();
        if (c + NSTAGE - 1 < NC) ISSUE_STAGE(c + NSTAGE - 1);
        CP_COMMIT();
        COMPUTE_STAGE(bufs_u + (c & (NSTAGE - 1)) * STAGE_B);
    }

    // epilogue: atomic fp16x2 accumulate into g_Ch[token]
#pragma unroll
    for (int mf = 0; mf < 4; mf++) {
        int m0l = wm * 64 + mf * 16 + (lane >> 2);
#pragma unroll
        for (int nf = 0; nf < 4; nf++) {
            int n = wn * 32 + nf * 8 + (lane & 3) * 2;
            const float* bep = be + e * D + n0 + n;
            float b0 = bep[0], b1 = bep[1];
#pragma unroll
            for (int half = 0; half < 2; half++) {
                int m = m0l + half * 8;
                int tk = sTok[m];
                if (tk >= 0) {
                    float w = sW[m];
                    __half2 o = __halves2half2(
                        __float2half_rn(w * (acc[mf][nf][half * 2 + 0] + b0)),
                        __float2half_rn(w * (acc[mf][nf][half * 2 + 1] + b1)));
                    atomicAdd((__half2*)(g_Ch + (size_t)tk * D + n0 + n), o);
                }
            }
        }
    }
}

// ---------------- output GEMM: out = C @ Wo^T + bo ---------------------------
__global__ __launch_bounds__(256, 2) void k_out_gemm(
    const float* __restrict__ bo, float* __restrict__ out)
{
    int m0 = blockIdx.y * 128;
    int n0 = blockIdx.x * 128;

    extern __shared__ char smem[];
    uint32_t bufs_u = smem_u32(smem + 1024);

    int tid = threadIdx.x, lane = tid & 31, warp = tid >> 5;
    int wm = warp >> 2, wn = warp & 3;

    SETUP_LDSM_OFFS();

    const __half* segp[4];
    int dstoff[4];
#pragma unroll
    for (int i = 0; i < 4; i++) {
        int seg = i * 256 + tid;
        int part = seg >> 9;
        int r = (seg >> 2) & 127;
        int s = seg & 3;
        dstoff[i] = part * 8192 + (s >> 1) * 4096 + swz(r, s & 1);
        if (part == 0)
            segp[i] = g_Ch + (size_t)(m0 + r) * D + s * 8;
        else
            segp[i] = g_Woh + (size_t)(n0 + r) * D + s * 8;
    }

    float acc[4][4][4];
#pragma unroll
    for (int mf = 0; mf < 4; mf++)
#pragma unroll
        for (int nf = 0; nf < 4; nf++)
#pragma unroll
            for (int q = 0; q < 4; q++) acc[mf][nf][q] = 0.f;

#pragma unroll
    for (int s = 0; s < NSTAGE - 1; s++) { ISSUE_STAGE(s); CP_COMMIT(); }

    for (int c = 0; c < NC; c++) {
        CP_WAIT2();
        __syncthreads();
        if (c + NSTAGE - 1 < NC) ISSUE_STAGE(c + NSTAGE - 1);
        CP_COMMIT();
        COMPUTE_STAGE(bufs_u + (c & (NSTAGE - 1)) * STAGE_B);
    }

#pragma unroll
    for (int mf = 0; mf < 4; mf++) {
        int m0l = wm * 64 + mf * 16 + (lane >> 2);
#pragma unroll
        for (int nf = 0; nf < 4; nf++) {
            int n = wn * 32 + nf * 8 + (lane & 3) * 2;
            const float* bop = bo + n0 + n;
            float b0 = bop[0], b1 = bop[1];
#pragma unroll
            for (int half = 0; half < 2; half++) {
                int m = m0l + half * 8;
                float2 o;
                o.x = acc[mf][nf][half * 2 + 0] + b0;
                o.y = acc[mf][nf][half * 2 + 1] + b1;
                *(float2*)(out + (size_t)(m0 + m) * D + n0 + n) = o;
            }
        }
    }
}

// ---------------- launch -----------------------------------------------------
extern "C" void kernel_launch(void* const* d_in, const int* in_sizes, int n_in,
                              void* d_out, int out_size)
{
    const float* X  = (const float*)d_in[0];
    const float* We = (const float*)d_in[1];
    const float* be = (const float*)d_in[2];
    const float* Wr = (const float*)d_in[3];
    const float* br = (const float*)d_in[4];
    const float* Wo = (const float*)d_in[5];
    const float* bo = (const float*)d_in[6];
    float* out = (float*)d_out;

    static int smem_set = 0;
    if (!smem_set) {
        cudaFuncSetAttribute(k_expert_gemm, cudaFuncAttributeMaxDynamicSharedMemorySize, SMEM_DYN);
        cudaFuncSetAttribute(k_out_gemm,    cudaFuncAttributeMaxDynamicSharedMemorySize, SMEM_DYN);
        smem_set = 1;
    }

    __half *weh, *woh, *ch;
    cudaGetSymbolAddress((void**)&weh, g_Weh);
    cudaGetSymbolAddress((void**)&woh, g_Woh);
    cudaGetSymbolAddress((void**)&ch,  g_Ch);

    k_init<<<1, 32>>>();
    cudaMemsetAsync(ch, 0, (size_t)T * D * sizeof(__half));
    k_convert_h<<<2048, 256>>>((const float4*)We, (uint2*)weh, E * D * D / 4);
    k_convert_h<<<512,  256>>>((const float4*)Wo, (uint2*)woh, D * D / 4);
    k_router<<<T / 8, 256>>>(X, Wr, br);
    k_scan<<<1, 1>>>();
    k_scatter<<<(2 * T) / 256, 256>>>();
    k_expert_gemm<<<dim3(D / 128, T / 128, E), 256, SMEM_DYN>>>(be);
    k_out_gemm<<<dim3(D / 128, T / 128), 256, SMEM_DYN>>>(bo, out);
}

// round 10
// speedup vs baseline: 1.0613x; 1.0613x over previous
#include <cuda_runtime.h>
#include <cuda_fp16.h>
#include <math.h>
#include <stdint.h>

#define T 16384          // B*S tokens
#define D 1024
#define E 8
#define ROWCAP (2*T + E*128)
#define KCH 32           // k per pipeline stage
#define NC (D/KCH)       // 32 chunks
#define NSTAGE 4
// per-stage layout (bytes): Ahi[2][4096] Bhi[2][4096]
#define STAGE_B 16384
#define SMEM_DYN (1024 + NSTAGE*STAGE_B)

// ---------------- scratch ----------------------------------------------------
__device__ int   g_counts[E];
__device__ int   g_cursor[E];
__device__ int   g_off[E];
__device__ int   g_topk_e[2*T];
__device__ float g_topk_w[2*T];
__device__ int   g_perm[ROWCAP];
__device__ float g_permw[ROWCAP];
__device__ int   g_slot[2*T];
__device__ __half g_Yh[(size_t)ROWCAP * D];   // fp16 expert outputs (weighted+biased)
// preconverted fp16 operands
__device__ __half g_Xh[(size_t)T*D];
__device__ __half g_Weh[(size_t)E*D*D];
__device__ __half g_Woh[(size_t)D*D];
__device__ __half g_Ch[(size_t)T*D];

// ---------------- helpers ----------------------------------------------------
__device__ __forceinline__ uint32_t smem_u32(const void* p) {
    uint32_t a;
    asm("{ .reg .u64 t; cvta.to.shared.u64 t, %1; cvt.u32.u64 %0, t; }" : "=r"(a) : "l"(p));
    return a;
}

__device__ __forceinline__ void ldsm4(uint32_t* r, uint32_t a) {
    asm volatile("ldmatrix.sync.aligned.m8n8.x4.shared.b16 {%0,%1,%2,%3}, [%4];"
        : "=r"(r[0]), "=r"(r[1]), "=r"(r[2]), "=r"(r[3]) : "r"(a));
}

__device__ __forceinline__ void mma_f16(float* d, const uint32_t* a, const uint32_t* b) {
    asm volatile("mma.sync.aligned.m16n8k16.row.col.f32.f16.f16.f32 "
        "{%0,%1,%2,%3},{%4,%5,%6,%7},{%8,%9},{%0,%1,%2,%3};"
        : "+f"(d[0]), "+f"(d[1]), "+f"(d[2]), "+f"(d[3])
        : "r"(a[0]), "r"(a[1]), "r"(a[2]), "r"(a[3]), "r"(b[0]), "r"(b[1]));
}

__device__ __forceinline__ void cp16(uint32_t dst, const void* src) {
    asm volatile("cp.async.cg.shared.global [%0], [%1], 16;" :: "r"(dst), "l"(src));
}
#define CP_COMMIT() asm volatile("cp.async.commit_group;" ::: "memory")
#define CP_WAIT2()  asm volatile("cp.async.wait_group 2;" ::: "memory")

// swizzled byte offset within a 4KB (128 rows x 32B) k16 sub-tile
__device__ __forceinline__ int swz(int r, int h) {
    return (((r << 1) | h) ^ ((r >> 2) & 1)) << 4;
}

__device__ __forceinline__ uint2 pack4h(float4 v) {
    unsigned short h0 = __half_as_ushort(__float2half_rn(v.x));
    unsigned short h1 = __half_as_ushort(__float2half_rn(v.y));
    unsigned short h2 = __half_as_ushort(__float2half_rn(v.z));
    unsigned short h3 = __half_as_ushort(__float2half_rn(v.w));
    return make_uint2((uint32_t)h0 | ((uint32_t)h1 << 16),
                      (uint32_t)h2 | ((uint32_t)h3 << 16));
}

// ---------------- convert: fp32 -> fp16 --------------------------------------
__global__ __launch_bounds__(256) void k_convert_h(
    const float4* __restrict__ in, uint2* __restrict__ hi, int n4)
{
    for (int i = blockIdx.x * 256 + threadIdx.x; i < n4; i += gridDim.x * 256)
        hi[i] = pack4h(in[i]);
}

// ---------------- init / router(+X convert) / scan / scatter -----------------
__global__ void k_init() {
    int i = threadIdx.x;
    if (i < E) { g_counts[i] = 0; g_cursor[i] = 0; }
}

__global__ __launch_bounds__(256) void k_router(
    const float* __restrict__ X, const float* __restrict__ Wr,
    const float* __restrict__ br)
{
    __shared__ float4 sWr[E * D / 4];
    int tid = threadIdx.x;
    for (int i = tid; i < E * D / 4; i += 256) sWr[i] = ((const float4*)Wr)[i];
    __syncthreads();

    int warp = tid >> 5, lane = tid & 31;
    int t = blockIdx.x * 8 + warp;

    const float4* xi = (const float4*)(X + (size_t)t * D);
    uint2* xo = (uint2*)(g_Xh + (size_t)t * D);

    float acc[E];
#pragma unroll
    for (int e = 0; e < E; e++) acc[e] = 0.f;

    // single pass: convert to fp16 AND accumulate router logits
#pragma unroll 2
    for (int i = 0; i < D / 4 / 32; i++) {
        int idx = i * 32 + lane;
        float4 v = xi[idx];
        xo[idx] = pack4h(v);
#pragma unroll
        for (int e = 0; e < E; e++) {
            float4 w = sWr[e * (D / 4) + idx];
            acc[e] += v.x * w.x + v.y * w.y + v.z * w.z + v.w * w.w;
        }
    }
#pragma unroll
    for (int e = 0; e < E; e++) {
#pragma unroll
        for (int o = 16; o > 0; o >>= 1)
            acc[e] += __shfl_xor_sync(0xffffffffu, acc[e], o);
    }
    if (lane == 0) {
        float p[E], m = -1e30f;
#pragma unroll
        for (int e = 0; e < E; e++) { p[e] = acc[e] + br[e]; m = fmaxf(m, p[e]); }
        float s = 0.f;
#pragma unroll
        for (int e = 0; e < E; e++) { p[e] = expf(p[e] - m); s += p[e]; }
        float inv = 1.f / s;
#pragma unroll
        for (int e = 0; e < E; e++) p[e] *= inv;
        int e0 = 0;
#pragma unroll
        for (int e = 1; e < E; e++) if (p[e] > p[e0]) e0 = e;
        int e1 = (e0 == 0) ? 1 : 0;
#pragma unroll
        for (int e = 0; e < E; e++) if (e != e0 && p[e] > p[e1]) e1 = e;
        g_topk_e[2 * t + 0] = e0;  g_topk_w[2 * t + 0] = p[e0];
        g_topk_e[2 * t + 1] = e1;  g_topk_w[2 * t + 1] = p[e1];
        atomicAdd(&g_counts[e0], 1);
        atomicAdd(&g_counts[e1], 1);
    }
}

__global__ void k_scan() {
    if (threadIdx.x == 0) {
        int off = 0;
        for (int e = 0; e < E; e++) {
            g_off[e] = off;
            off += ((g_counts[e] + 127) / 128) * 128;
        }
    }
}

// warp-aggregated scatter: one atomic per (warp, expert)
__global__ __launch_bounds__(256) void k_scatter() {
    int idx = blockIdx.x * 256 + threadIdx.x;
    int lane = threadIdx.x & 31;
    if (idx >= 2 * T) return;
    int e = g_topk_e[idx];
    float w = g_topk_w[idx];
    unsigned mask = __match_any_sync(0xffffffffu, e);
    int leader = __ffs(mask) - 1;
    int rank = __popc(mask & ((1u << lane) - 1));
    int base = 0;
    if (lane == leader) base = atomicAdd(&g_cursor[e], __popc(mask));
    base = __shfl_sync(0xffffffffu, base, leader);
    int slot = g_off[e] + base + rank;
    g_perm[slot]  = idx >> 1;
    g_permw[slot] = w;
    g_slot[idx]   = slot;
}

// ---------------- combine: C[t] = Yh[s0] + Yh[s1] (fp16, 16B wide) -----------
__global__ __launch_bounds__(256) void k_combine() {
    int idx = blockIdx.x * 256 + threadIdx.x;        // over T*D/8
    int t = idx >> 7;                                 // D/8 = 128 uint4/row
    int c8 = idx & 127;
    int s0 = g_slot[2 * t + 0], s1 = g_slot[2 * t + 1];
    uint4 a = ((const uint4*)g_Yh)[(size_t)s0 * 128 + c8];
    uint4 b = ((const uint4*)g_Yh)[(size_t)s1 * 128 + c8];
    __half2 r0 = __hadd2(*(__half2*)&a.x, *(__half2*)&b.x);
    __half2 r1 = __hadd2(*(__half2*)&a.y, *(__half2*)&b.y);
    __half2 r2 = __hadd2(*(__half2*)&a.z, *(__half2*)&b.z);
    __half2 r3 = __hadd2(*(__half2*)&a.w, *(__half2*)&b.w);
    uint4 o;
    o.x = *(uint32_t*)&r0; o.y = *(uint32_t*)&r1;
    o.z = *(uint32_t*)&r2; o.w = *(uint32_t*)&r3;
    ((uint4*)g_Ch)[idx] = o;
}

// ===== shared compute: 2 k16 steps, single-pass fp16 =========================
#define COMPUTE_STAGE(bufbase)                                                \
    do {                                                                      \
        _Pragma("unroll")                                                     \
        for (int ks = 0; ks < 2; ks++) {                                      \
            uint32_t ahB = (bufbase) + ks * 4096;                             \
            uint32_t bhB = (bufbase) + 8192 + ks * 4096;                      \
            uint32_t ahi[4][4], bhi[2][4];                                    \
            _Pragma("unroll")                                                 \
            for (int mf = 0; mf < 4; mf++) ldsm4(ahi[mf], ahB + aoff[mf]);    \
            _Pragma("unroll")                                                 \
            for (int p = 0; p < 2; p++) ldsm4(bhi[p], bhB + boff[p]);         \
            _Pragma("unroll")                                                 \
            for (int mf = 0; mf < 4; mf++)                                    \
                _Pragma("unroll")                                             \
                for (int nf = 0; nf < 4; nf++)                                \
                    mma_f16(acc[mf][nf], ahi[mf], &bhi[nf >> 1][(nf & 1) * 2]); \
        }                                                                     \
    } while (0)

#define SETUP_LDSM_OFFS()                                                     \
    int aoff[4], boff[2];                                                     \
    {                                                                         \
        int ar = lane & 15, ah = lane >> 4;                                   \
        _Pragma("unroll")                                                     \
        for (int mf = 0; mf < 4; mf++) aoff[mf] = swz(wm * 64 + mf * 16 + ar, ah); \
        int bj = lane >> 3;                                                   \
        int bn = (lane & 7) + ((bj >> 1) << 3);                               \
        int bh_ = bj & 1;                                                     \
        _Pragma("unroll")                                                     \
        for (int p = 0; p < 2; p++) boff[p] = swz(wn * 32 + p * 16 + bn, bh_);\
    }

// 4 x 16B segments per thread per stage: part = seg>>9 (0=Ahi,1=Bhi)
#define ISSUE_STAGE(c)                                                        \
    do {                                                                      \
        uint32_t _sb = bufs_u + ((c) & (NSTAGE - 1)) * STAGE_B;               \
        int _k0 = (c) * KCH;                                                  \
        _Pragma("unroll")                                                     \
        for (int i = 0; i < 4; i++) cp16(_sb + dstoff[i], segp[i] + _k0);     \
    } while (0)

// ---------------- expert GEMM: Yh[slot] = fp16(w*(X[tok]@We[e]^T+be[e])) -----
__global__ __launch_bounds__(256, 2) void k_expert_gemm(const float* __restrict__ be)
{
    int e = blockIdx.z;
    int cnt = g_counts[e];
    int row0 = blockIdx.y * 128;
    if (row0 >= cnt) return;
    int n0 = blockIdx.x * 128;
    int off = g_off[e];

    extern __shared__ char smem[];
    int* sTok = (int*)smem;
    float* sW = (float*)(smem + 512);
    uint32_t bufs_u = smem_u32(smem + 1024);

    int tid = threadIdx.x, lane = tid & 31, warp = tid >> 5;
    int wm = warp >> 2, wn = warp & 3;
    const __half* Whi = g_Weh + (size_t)e * D * D;

    if (tid < 128) {
        int rl = row0 + tid;
        bool v = rl < cnt;
        sTok[tid] = v ? g_perm[off + rl] : -1;
        sW[tid]   = v ? g_permw[off + rl] : 0.f;
    }
    __syncthreads();

    SETUP_LDSM_OFFS();

    const __half* segp[4];
    int dstoff[4];
#pragma unroll
    for (int i = 0; i < 4; i++) {
        int seg = i * 256 + tid;
        int part = seg >> 9;
        int r = (seg >> 2) & 127;
        int s = seg & 3;
        dstoff[i] = part * 8192 + (s >> 1) * 4096 + swz(r, s & 1);
        if (part == 0) {
            int tk = sTok[r]; if (tk < 0) tk = 0;   // garbage row masked in epilogue
            segp[i] = g_Xh + (size_t)tk * D + s * 8;
        } else {
            segp[i] = Whi + (size_t)(n0 + r) * D + s * 8;
        }
    }

    float acc[4][4][4];
#pragma unroll
    for (int mf = 0; mf < 4; mf++)
#pragma unroll
        for (int nf = 0; nf < 4; nf++)
#pragma unroll
            for (int q = 0; q < 4; q++) acc[mf][nf][q] = 0.f;

#pragma unroll
    for (int s = 0; s < NSTAGE - 1; s++) { ISSUE_STAGE(s); CP_COMMIT(); }

    for (int c = 0; c < NC; c++) {
        CP_WAIT2();
        __syncthreads();
        if (c + NSTAGE - 1 < NC) ISSUE_STAGE(c + NSTAGE - 1);
        CP_COMMIT();
        COMPUTE_STAGE(bufs_u + (c & (NSTAGE - 1)) * STAGE_B);
    }

    // epilogue (fp16 Y)
#pragma unroll
    for (int mf = 0; mf < 4; mf++) {
        int m0l = wm * 64 + mf * 16 + (lane >> 2);
#pragma unroll
        for (int nf = 0; nf < 4; nf++) {
            int n = wn * 32 + nf * 8 + (lane & 3) * 2;
            const float* bep = be + e * D + n0 + n;
            float b0 = bep[0], b1 = bep[1];
#pragma unroll
            for (int half = 0; half < 2; half++) {
                int m = m0l + half * 8;
                if (sTok[m] >= 0) {
                    float w = sW[m];
                    __half2 o = __halves2half2(
                        __float2half_rn(w * (acc[mf][nf][half * 2 + 0] + b0)),
                        __float2half_rn(w * (acc[mf][nf][half * 2 + 1] + b1)));
                    *(__half2*)(g_Yh + (size_t)(off + row0 + m) * D + n0 + n) = o;
                }
            }
        }
    }
}

// ---------------- output GEMM: out = C @ Wo^T + bo ---------------------------
__global__ __launch_bounds__(256, 2) void k_out_gemm(
    const float* __restrict__ bo, float* __restrict__ out)
{
    int m0 = blockIdx.y * 128;
    int n0 = blockIdx.x * 128;

    extern __shared__ char smem[];
    uint32_t bufs_u = smem_u32(smem + 1024);

    int tid = threadIdx.x, lane = tid & 31, warp = tid >> 5;
    int wm = warp >> 2, wn = warp & 3;

    SETUP_LDSM_OFFS();

    const __half* segp[4];
    int dstoff[4];
#pragma unroll
    for (int i = 0; i < 4; i++) {
        int seg = i * 256 + tid;
        int part = seg >> 9;
        int r = (seg >> 2) & 127;
        int s = seg & 3;
        dstoff[i] = part * 8192 + (s >> 1) * 4096 + swz(r, s & 1);
        if (part == 0)
            segp[i] = g_Ch + (size_t)(m0 + r) * D + s * 8;
        else
            segp[i] = g_Woh + (size_t)(n0 + r) * D + s * 8;
    }

    float acc[4][4][4];
#pragma unroll
    for (int mf = 0; mf < 4; mf++)
#pragma unroll
        for (int nf = 0; nf < 4; nf++)
#pragma unroll
            for (int q = 0; q < 4; q++) acc[mf][nf][q] = 0.f;

#pragma unroll
    for (int s = 0; s < NSTAGE - 1; s++) { ISSUE_STAGE(s); CP_COMMIT(); }

    for (int c = 0; c < NC; c++) {
        CP_WAIT2();
        __syncthreads();
        if (c + NSTAGE - 1 < NC) ISSUE_STAGE(c + NSTAGE - 1);
        CP_COMMIT();
        COMPUTE_STAGE(bufs_u + (c & (NSTAGE - 1)) * STAGE_B);
    }

#pragma unroll
    for (int mf = 0; mf < 4; mf++) {
        int m0l = wm * 64 + mf * 16 + (lane >> 2);
#pragma unroll
        for (int nf = 0; nf < 4; nf++) {
            int n = wn * 32 + nf * 8 + (lane & 3) * 2;
            const float* bop = bo + n0 + n;
            float b0 = bop[0], b1 = bop[1];
#pragma unroll
            for (int half = 0; half < 2; half++) {
                int m = m0l + half * 8;
                float2 o;
                o.x = acc[mf][nf][half * 2 + 0] + b0;
                o.y = acc[mf][nf][half * 2 + 1] + b1;
                *(float2*)(out + (size_t)(m0 + m) * D + n0 + n) = o;
            }
        }
    }
}

// ---------------- launch -----------------------------------------------------
extern "C" void kernel_launch(void* const* d_in, const int* in_sizes, int n_in,
                              void* d_out, int out_size)
{
    const float* X  = (const float*)d_in[0];
    const float* We = (const float*)d_in[1];
    const float* be = (const float*)d_in[2];
    const float* Wr = (const float*)d_in[3];
    const float* br = (const float*)d_in[4];
    const float* Wo = (const float*)d_in[5];
    const float* bo = (const float*)d_in[6];
    float* out = (float*)d_out;

    static int inited = 0;
    static cudaStream_t s1;
    static cudaEvent_t evFork, evJoin;
    if (!inited) {
        cudaFuncSetAttribute(k_expert_gemm, cudaFuncAttributeMaxDynamicSharedMemorySize, SMEM_DYN);
        cudaFuncSetAttribute(k_out_gemm,    cudaFuncAttributeMaxDynamicSharedMemorySize, SMEM_DYN);
        cudaStreamCreateWithFlags(&s1, cudaStreamNonBlocking);
        cudaEventCreateWithFlags(&evFork, cudaEventDisableTiming);
        cudaEventCreateWithFlags(&evJoin, cudaEventDisableTiming);
        inited = 1;
    }

    __half *weh, *woh;
    cudaGetSymbolAddress((void**)&weh, g_Weh);
    cudaGetSymbolAddress((void**)&woh, g_Woh);

    k_init<<<1, 32>>>();
    // fork: weight converts on side stream, overlapped with router/scan/scatter
    cudaEventRecord(evFork, 0);
    cudaStreamWaitEvent(s1, evFork, 0);
    k_convert_h<<<2048, 256, 0, s1>>>((const float4*)We, (uint2*)weh, E * D * D / 4);
    k_convert_h<<<512,  256, 0, s1>>>((const float4*)Wo, (uint2*)woh, D * D / 4);
    cudaEventRecord(evJoin, s1);

    k_router<<<T / 8, 256>>>(X, Wr, br);
    k_scan<<<1, 1>>>();
    k_scatter<<<(2 * T) / 256, 256>>>();

    // join: expert GEMM needs Weh
    cudaStreamWaitEvent(0, evJoin, 0);
    k_expert_gemm<<<dim3(D / 128, T / 128, E), 256, SMEM_DYN>>>(be);
    k_combine<<<T * D / 8 / 256, 256>>>();
    k_out_gemm<<<dim3(D / 128, T / 128), 256, SMEM_DYN>>>(bo, out);
}

// round 11
// speedup vs baseline: 1.0707x; 1.0089x over previous
#include <cuda_runtime.h>
#include <cuda_fp16.h>
#include <math.h>
#include <stdint.h>

#define T 16384          // B*S tokens
#define D 1024
#define E 8
#define ROWCAP (2*T + E*128)
#define KCH 32           // k per pipeline stage
#define NC (D/KCH)       // 32 chunks
#define NSTAGE 4
// per-stage layout (bytes): Ahi[2][4096] Bhi[2][4096]
#define STAGE_B 16384
#define SMEM_DYN (1024 + NSTAGE*STAGE_B)

// ---------------- scratch ----------------------------------------------------
__device__ int   g_counts[E];
__device__ int   g_cursor[E];
__device__ int   g_off[E];
__device__ int   g_topk_e[2*T];
__device__ float g_topk_w[2*T];
__device__ int   g_perm[ROWCAP];
__device__ float g_permw[ROWCAP];
__device__ int   g_slot[2*T];
__device__ __half g_Yh[(size_t)ROWCAP * D];   // fp16 expert outputs (weighted+biased)
// preconverted fp16 operands
__device__ __half g_Xh[(size_t)T*D];
__device__ __half g_Weh[(size_t)E*D*D];
__device__ __half g_Woh[(size_t)D*D];
__device__ __half g_Ch[(size_t)T*D];

// ---------------- helpers ----------------------------------------------------
__device__ __forceinline__ uint32_t smem_u32(const void* p) {
    uint32_t a;
    asm("{ .reg .u64 t; cvta.to.shared.u64 t, %1; cvt.u32.u64 %0, t; }" : "=r"(a) : "l"(p));
    return a;
}

__device__ __forceinline__ void ldsm4(uint32_t* r, uint32_t a) {
    asm volatile("ldmatrix.sync.aligned.m8n8.x4.shared.b16 {%0,%1,%2,%3}, [%4];"
        : "=r"(r[0]), "=r"(r[1]), "=r"(r[2]), "=r"(r[3]) : "r"(a));
}

__device__ __forceinline__ void mma_f16(float* d, const uint32_t* a, const uint32_t* b) {
    asm volatile("mma.sync.aligned.m16n8k16.row.col.f32.f16.f16.f32 "
        "{%0,%1,%2,%3},{%4,%5,%6,%7},{%8,%9},{%0,%1,%2,%3};"
        : "+f"(d[0]), "+f"(d[1]), "+f"(d[2]), "+f"(d[3])
        : "r"(a[0]), "r"(a[1]), "r"(a[2]), "r"(a[3]), "r"(b[0]), "r"(b[1]));
}

__device__ __forceinline__ void cp16(uint32_t dst, const void* src) {
    asm volatile("cp.async.cg.shared.global [%0], [%1], 16;" :: "r"(dst), "l"(src));
}
#define CP_COMMIT() asm volatile("cp.async.commit_group;" ::: "memory")
#define CP_WAIT2()  asm volatile("cp.async.wait_group 2;" ::: "memory")

// swizzled byte offset within a 4KB (128 rows x 32B) k16 sub-tile
__device__ __forceinline__ int swz(int r, int h) {
    return (((r << 1) | h) ^ ((r >> 2) & 1)) << 4;
}

__device__ __forceinline__ uint2 pack4h(float4 v) {
    unsigned short h0 = __half_as_ushort(__float2half_rn(v.x));
    unsigned short h1 = __half_as_ushort(__float2half_rn(v.y));
    unsigned short h2 = __half_as_ushort(__float2half_rn(v.z));
    unsigned short h3 = __half_as_ushort(__float2half_rn(v.w));
    return make_uint2((uint32_t)h0 | ((uint32_t)h1 << 16),
                      (uint32_t)h2 | ((uint32_t)h3 << 16));
}

// ---------------- convert: fp32 -> fp16 (two arrays, one launch) -------------
__global__ __launch_bounds__(256) void k_convert_w(
    const float4* __restrict__ inA, uint2* __restrict__ outA, int nA,
    const float4* __restrict__ inB, uint2* __restrict__ outB, int nB)
{
    for (int i = blockIdx.x * 256 + threadIdx.x; i < nA + nB; i += gridDim.x * 256) {
        if (i < nA) outA[i] = pack4h(inA[i]);
        else        outB[i - nA] = pack4h(inB[i - nA]);
    }
}

// ---------------- init / router(+X convert) / scan / scatter -----------------
__global__ void k_init() {
    int i = threadIdx.x;
    if (i < E) { g_counts[i] = 0; g_cursor[i] = 0; }
}

// 2 tokens per warp: each sWr LDS is reused for both tokens (halves LDS traffic)
__global__ __launch_bounds__(256) void k_router(
    const float* __restrict__ X, const float* __restrict__ Wr,
    const float* __restrict__ br)
{
    __shared__ float4 sWr[E * D / 4];
    int tid = threadIdx.x;
    for (int i = tid; i < E * D / 4; i += 256) sWr[i] = ((const float4*)Wr)[i];
    __syncthreads();

    int warp = tid >> 5, lane = tid & 31;
    int t0 = blockIdx.x * 16 + warp * 2;      // this warp's two tokens

    const float4* xi0 = (const float4*)(X + (size_t)t0 * D);
    const float4* xi1 = (const float4*)(X + (size_t)(t0 + 1) * D);
    uint2* xo0 = (uint2*)(g_Xh + (size_t)t0 * D);
    uint2* xo1 = (uint2*)(g_Xh + (size_t)(t0 + 1) * D);

    float a0[E], a1[E];
#pragma unroll
    for (int e = 0; e < E; e++) { a0[e] = 0.f; a1[e] = 0.f; }

    // single pass: convert both rows to fp16 AND accumulate both logit sets
    for (int i = 0; i < D / 4 / 32; i++) {
        int idx = i * 32 + lane;
        float4 v0 = xi0[idx];
        float4 v1 = xi1[idx];
        xo0[idx] = pack4h(v0);
        xo1[idx] = pack4h(v1);
#pragma unroll
        for (int e = 0; e < E; e++) {
            float4 w = sWr[e * (D / 4) + idx];
            a0[e] += v0.x * w.x + v0.y * w.y + v0.z * w.z + v0.w * w.w;
            a1[e] += v1.x * w.x + v1.y * w.y + v1.z * w.z + v1.w * w.w;
        }
    }
    // butterfly reduce: all lanes end with full sums
#pragma unroll
    for (int e = 0; e < E; e++) {
#pragma unroll
        for (int o = 16; o > 0; o >>= 1) {
            a0[e] += __shfl_xor_sync(0xffffffffu, a0[e], o);
            a1[e] += __shfl_xor_sync(0xffffffffu, a1[e], o);
        }
    }
    // lane 0 finalizes t0, lane 1 finalizes t0+1 (in parallel)
    if (lane < 2) {
        int t = t0 + lane;
        float p[E], m = -1e30f;
#pragma unroll
        for (int e = 0; e < E; e++) {
            p[e] = (lane == 0 ? a0[e] : a1[e]) + br[e];
            m = fmaxf(m, p[e]);
        }
        float s = 0.f;
#pragma unroll
        for (int e = 0; e < E; e++) { p[e] = expf(p[e] - m); s += p[e]; }
        float inv = 1.f / s;
#pragma unroll
        for (int e = 0; e < E; e++) p[e] *= inv;
        int e0 = 0;
#pragma unroll
        for (int e = 1; e < E; e++) if (p[e] > p[e0]) e0 = e;
        int e1 = (e0 == 0) ? 1 : 0;
#pragma unroll
        for (int e = 0; e < E; e++) if (e != e0 && p[e] > p[e1]) e1 = e;
        g_topk_e[2 * t + 0] = e0;  g_topk_w[2 * t + 0] = p[e0];
        g_topk_e[2 * t + 1] = e1;  g_topk_w[2 * t + 1] = p[e1];
        atomicAdd(&g_counts[e0], 1);
        atomicAdd(&g_counts[e1], 1);
    }
}

__global__ void k_scan() {
    if (threadIdx.x == 0) {
        int off = 0;
        for (int e = 0; e < E; e++) {
            g_off[e] = off;
            off += ((g_counts[e] + 127) / 128) * 128;
        }
    }
}

// warp-aggregated scatter: one atomic per (warp, expert)
__global__ __launch_bounds__(256) void k_scatter() {
    int idx = blockIdx.x * 256 + threadIdx.x;
    int lane = threadIdx.x & 31;
    if (idx >= 2 * T) return;
    int e = g_topk_e[idx];
    float w = g_topk_w[idx];
    unsigned mask = __match_any_sync(0xffffffffu, e);
    int leader = __ffs(mask) - 1;
    int rank = __popc(mask & ((1u << lane) - 1));
    int base = 0;
    if (lane == leader) base = atomicAdd(&g_cursor[e], __popc(mask));
    base = __shfl_sync(0xffffffffu, base, leader);
    int slot = g_off[e] + base + rank;
    g_perm[slot]  = idx >> 1;
    g_permw[slot] = w;
    g_slot[idx]   = slot;
}

// ---------------- combine: C[t] = Yh[s0] + Yh[s1] (fp16, 16B wide) -----------
__global__ __launch_bounds__(256) void k_combine() {
    int idx = blockIdx.x * 256 + threadIdx.x;        // over T*D/8
    int t = idx >> 7;                                 // D/8 = 128 uint4/row
    int c8 = idx & 127;
    int s0 = g_slot[2 * t + 0], s1 = g_slot[2 * t + 1];
    uint4 a = ((const uint4*)g_Yh)[(size_t)s0 * 128 + c8];
    uint4 b = ((const uint4*)g_Yh)[(size_t)s1 * 128 + c8];
    __half2 r0 = __hadd2(*(__half2*)&a.x, *(__half2*)&b.x);
    __half2 r1 = __hadd2(*(__half2*)&a.y, *(__half2*)&b.y);
    __half2 r2 = __hadd2(*(__half2*)&a.z, *(__half2*)&b.z);
    __half2 r3 = __hadd2(*(__half2*)&a.w, *(__half2*)&b.w);
    uint4 o;
    o.x = *(uint32_t*)&r0; o.y = *(uint32_t*)&r1;
    o.z = *(uint32_t*)&r2; o.w = *(uint32_t*)&r3;
    ((uint4*)g_Ch)[idx] = o;
}

// ===== shared compute: 2 k16 steps, single-pass fp16 =========================
#define COMPUTE_STAGE(bufbase)                                                \
    do {                                                                      \
        _Pragma("unroll")                                                     \
        for (int ks = 0; ks < 2; ks++) {                                      \
            uint32_t ahB = (bufbase) + ks * 4096;                             \
            uint32_t bhB = (bufbase) + 8192 + ks * 4096;                      \
            uint32_t ahi[4][4], bhi[2][4];                                    \
            _Pragma("unroll")                                                 \
            for (int mf = 0; mf < 4; mf++) ldsm4(ahi[mf], ahB + aoff[mf]);    \
            _Pragma("unroll")                                                 \
            for (int p = 0; p < 2; p++) ldsm4(bhi[p], bhB + boff[p]);         \
            _Pragma("unroll")                                                 \
            for (int mf = 0; mf < 4; mf++)                                    \
                _Pragma("unroll")                                             \
                for (int nf = 0; nf < 4; nf++)                                \
                    mma_f16(acc[mf][nf], ahi[mf], &bhi[nf >> 1][(nf & 1) * 2]); \
        }                                                                     \
    } while (0)

#define SETUP_LDSM_OFFS()                                                     \
    int aoff[4], boff[2];                                                     \
    {                                                                         \
        int ar = lane & 15, ah = lane >> 4;                                   \
        _Pragma("unroll")                                                     \
        for (int mf = 0; mf < 4; mf++) aoff[mf] = swz(wm * 64 + mf * 16 + ar, ah); \
        int bj = lane >> 3;                                                   \
        int bn = (lane & 7) + ((bj >> 1) << 3);                               \
        int bh_ = bj & 1;                                                     \
        _Pragma("unroll")                                                     \
        for (int p = 0; p < 2; p++) boff[p] = swz(wn * 32 + p * 16 + bn, bh_);\
    }

// 4 x 16B segments per thread per stage: part = seg>>9 (0=Ahi,1=Bhi)
#define ISSUE_STAGE(c)                                                        \
    do {                                                                      \
        uint32_t _sb = bufs_u + ((c) & (NSTAGE - 1)) * STAGE_B;               \
        int _k0 = (c) * KCH;                                                  \
        _Pragma("unroll")                                                     \
        for (int i = 0; i < 4; i++) cp16(_sb + dstoff[i], segp[i] + _k0);     \
    } while (0)

// ---------------- expert GEMM: Yh[slot] = fp16(w*(X[tok]@We[e]^T+be[e])) -----
__global__ __launch_bounds__(256, 2) void k_expert_gemm(const float* __restrict__ be)
{
    int e = blockIdx.z;
    int cnt = g_counts[e];
    int row0 = blockIdx.y * 128;
    if (row0 >= cnt) return;
    int n0 = blockIdx.x * 128;
    int off = g_off[e];

    extern __shared__ char smem[];
    int* sTok = (int*)smem;
    float* sW = (float*)(smem + 512);
    uint32_t bufs_u = smem_u32(smem + 1024);

    int tid = threadIdx.x, lane = tid & 31, warp = tid >> 5;
    int wm = warp >> 2, wn = warp & 3;
    const __half* Whi = g_Weh + (size_t)e * D * D;

    if (tid < 128) {
        int rl = row0 + tid;
        bool v = rl < cnt;
        sTok[tid] = v ? g_perm[off + rl] : -1;
        sW[tid]   = v ? g_permw[off + rl] : 0.f;
    }
    __syncthreads();

    SETUP_LDSM_OFFS();

    const __half* segp[4];
    int dstoff[4];
#pragma unroll
    for (int i = 0; i < 4; i++) {
        int seg = i * 256 + tid;
        int part = seg >> 9;
        int r = (seg >> 2) & 127;
        int s = seg & 3;
        dstoff[i] = part * 8192 + (s >> 1) * 4096 + swz(r, s & 1);
        if (part == 0) {
            int tk = sTok[r]; if (tk < 0) tk = 0;   // garbage row masked in epilogue
            segp[i] = g_Xh + (size_t)tk * D + s * 8;
        } else {
            segp[i] = Whi + (size_t)(n0 + r) * D + s * 8;
        }
    }

    float acc[4][4][4];
#pragma unroll
    for (int mf = 0; mf < 4; mf++)
#pragma unroll
        for (int nf = 0; nf < 4; nf++)
#pragma unroll
            for (int q = 0; q < 4; q++) acc[mf][nf][q] = 0.f;

#pragma unroll
    for (int s = 0; s < NSTAGE - 1; s++) { ISSUE_STAGE(s); CP_COMMIT(); }

    for (int c = 0; c < NC; c++) {
        CP_WAIT2();
        __syncthreads();
        if (c + NSTAGE - 1 < NC) ISSUE_STAGE(c + NSTAGE - 1);
        CP_COMMIT();
        COMPUTE_STAGE(bufs_u + (c & (NSTAGE - 1)) * STAGE_B);
    }

    // epilogue (fp16 Y)
#pragma unroll
    for (int mf = 0; mf < 4; mf++) {
        int m0l = wm * 64 + mf * 16 + (lane >> 2);
#pragma unroll
        for (int nf = 0; nf < 4; nf++) {
            int n = wn * 32 + nf * 8 + (lane & 3) * 2;
            const float* bep = be + e * D + n0 + n;
            float b0 = bep[0], b1 = bep[1];
#pragma unroll
            for (int half = 0; half < 2; half++) {
                int m = m0l + half * 8;
                if (sTok[m] >= 0) {
                    float w = sW[m];
                    __half2 o = __halves2half2(
                        __float2half_rn(w * (acc[mf][nf][half * 2 + 0] + b0)),
                        __float2half_rn(w * (acc[mf][nf][half * 2 + 1] + b1)));
                    *(__half2*)(g_Yh + (size_t)(off + row0 + m) * D + n0 + n) = o;
                }
            }
        }
    }
}

// ---------------- output GEMM: out = C @ Wo^T + bo ---------------------------
__global__ __launch_bounds__(256, 2) void k_out_gemm(
    const float* __restrict__ bo, float* __restrict__ out)
{
    int m0 = blockIdx.y * 128;
    int n0 = blockIdx.x * 128;

    extern __shared__ char smem[];
    uint32_t bufs_u = smem_u32(smem + 1024);

    int tid = threadIdx.x, lane = tid & 31, warp = tid >> 5;
    int wm = warp >> 2, wn = warp & 3;

    SETUP_LDSM_OFFS();

    const __half* segp[4];
    int dstoff[4];
#pragma unroll
    for (int i = 0; i < 4; i++) {
        int seg = i * 256 + tid;
        int part = seg >> 9;
        int r = (seg >> 2) & 127;
        int s = seg & 3;
        dstoff[i] = part * 8192 + (s >> 1) * 4096 + swz(r, s & 1);
        if (part == 0)
            segp[i] = g_Ch + (size_t)(m0 + r) * D + s * 8;
        else
            segp[i] = g_Woh + (size_t)(n0 + r) * D + s * 8;
    }

    float acc[4][4][4];
#pragma unroll
    for (int mf = 0; mf < 4; mf++)
#pragma unroll
        for (int nf = 0; nf < 4; nf++)
#pragma unroll
            for (int q = 0; q < 4; q++) acc[mf][nf][q] = 0.f;

#pragma unroll
    for (int s = 0; s < NSTAGE - 1; s++) { ISSUE_STAGE(s); CP_COMMIT(); }

    for (int c = 0; c < NC; c++) {
        CP_WAIT2();
        __syncthreads();
        if (c + NSTAGE - 1 < NC) ISSUE_STAGE(c + NSTAGE - 1);
        CP_COMMIT();
        COMPUTE_STAGE(bufs_u + (c & (NSTAGE - 1)) * STAGE_B);
    }

#pragma unroll
    for (int mf = 0; mf < 4; mf++) {
        int m0l = wm * 64 + mf * 16 + (lane >> 2);
#pragma unroll
        for (int nf = 0; nf < 4; nf++) {
            int n = wn * 32 + nf * 8 + (lane & 3) * 2;
            const float* bop = bo + n0 + n;
            float b0 = bop[0], b1 = bop[1];
#pragma unroll
            for (int half = 0; half < 2; half++) {
                int m = m0l + half * 8;
                float2 o;
                o.x = acc[mf][nf][half * 2 + 0] + b0;
                o.y = acc[mf][nf][half * 2 + 1] + b1;
                *(float2*)(out + (size_t)(m0 + m) * D + n0 + n) = o;
            }
        }
    }
}

// ---------------- launch -----------------------------------------------------
extern "C" void kernel_launch(void* const* d_in, const int* in_sizes, int n_in,
                              void* d_out, int out_size)
{
    const float* X  = (const float*)d_in[0];
    const float* We = (const float*)d_in[1];
    const float* be = (const float*)d_in[2];
    const float* Wr = (const float*)d_in[3];
    const float* br = (const float*)d_in[4];
    const float* Wo = (const float*)d_in[5];
    const float* bo = (const float*)d_in[6];
    float* out = (float*)d_out;

    static int inited = 0;
    static cudaStream_t s1;
    static cudaEvent_t evFork, evJoin;
    if (!inited) {
        cudaFuncSetAttribute(k_expert_gemm, cudaFuncAttributeMaxDynamicSharedMemorySize, SMEM_DYN);
        cudaFuncSetAttribute(k_out_gemm,    cudaFuncAttributeMaxDynamicSharedMemorySize, SMEM_DYN);
        cudaStreamCreateWithFlags(&s1, cudaStreamNonBlocking);
        cudaEventCreateWithFlags(&evFork, cudaEventDisableTiming);
        cudaEventCreateWithFlags(&evJoin, cudaEventDisableTiming);
        inited = 1;
    }

    __half *weh, *woh;
    cudaGetSymbolAddress((void**)&weh, g_Weh);
    cudaGetSymbolAddress((void**)&woh, g_Woh);

    k_init<<<1, 32>>>();
    // fork: weight converts on side stream, overlapped with router/scan/scatter
    cudaEventRecord(evFork, 0);
    cudaStreamWaitEvent(s1, evFork, 0);
    k_convert_w<<<2560, 256, 0, s1>>>((const float4*)We, (uint2*)weh, E * D * D / 4,
                                      (const float4*)Wo, (uint2*)woh, D * D / 4);
    cudaEventRecord(evJoin, s1);

    k_router<<<T / 16, 256>>>(X, Wr, br);
    k_scan<<<1, 1>>>();
    k_scatter<<<(2 * T) / 256, 256>>>();

    // join: expert GEMM needs Weh
    cudaStreamWaitEvent(0, evJoin, 0);
    k_expert_gemm<<<dim3(D / 128, T / 128, E), 256, SMEM_DYN>>>(be);
    k_combine<<<T * D / 8 / 256, 256>>>();
    k_out_gemm<<<dim3(D / 128, T / 128), 256, SMEM_DYN>>>(bo, out);
}